// round 7
// baseline (speedup 1.0000x reference)
#include <cuda_runtime.h>
#include <cuda_fp16.h>
#include <cstdint>
#include <math.h>

// ---------------- problem constants ----------------
#define T_TOKENS 4096
#define DDIM     1024
#define MDIM     1408
#define NEXP     8
#define BM       128
#define BN       64
#define BK       64
#define PAIRS_PAD 9216
#define NTILES   (PAIRS_PAD / BM)     // 72
#define G1_CH    (DDIM / BK)          // 16
#define G2_CH    (MDIM / BK)          // 22
#define RS       144                  // smem row stride: 64 fp16 = 128B + 16B skew

// ---------------- device scratch ----------------
__device__ __half g_Hf[(size_t)PAIRS_PAD * MDIM];
__device__ __half g_X16[(size_t)T_TOKENS * DDIM];
__device__ __half g_Wg16[(size_t)NEXP * DDIM * MDIM];
__device__ __half g_Wu16[(size_t)NEXP * DDIM * MDIM];
__device__ __half g_Wd16[(size_t)NEXP * MDIM * DDIM];
__device__ int   g_pair_tok[PAIRS_PAD];
__device__ float g_pair_p[PAIRS_PAD];
__device__ int   g_cnt[NEXP];
__device__ int   g_fill[NEXP];
__device__ int   g_segs[NEXP + 1];
__device__ int   g_tok_e[T_TOKENS * 2];
__device__ float g_tok_p[T_TOKENS * 2];

// ---------------- helpers ----------------
__device__ __forceinline__ uint32_t smem_u32(const void* p) {
    uint32_t a;
    asm("{ .reg .u64 t; cvta.to.shared.u64 t, %1; cvt.u32.u64 %0, t; }" : "=r"(a) : "l"(p));
    return a;
}
__device__ __forceinline__ void ldsm_x4(uint32_t* r, uint32_t addr) {
    asm volatile("ldmatrix.sync.aligned.m8n8.x4.shared.b16 {%0,%1,%2,%3}, [%4];"
        : "=r"(r[0]), "=r"(r[1]), "=r"(r[2]), "=r"(r[3]) : "r"(addr));
}
__device__ __forceinline__ void ldsm_x4_t(uint32_t* r, uint32_t addr) {
    asm volatile("ldmatrix.sync.aligned.m8n8.x4.trans.shared.b16 {%0,%1,%2,%3}, [%4];"
        : "=r"(r[0]), "=r"(r[1]), "=r"(r[2]), "=r"(r[3]) : "r"(addr));
}
__device__ __forceinline__ void mma16816(float* d, const uint32_t* a, const uint32_t* b) {
    asm volatile("mma.sync.aligned.m16n8k16.row.col.f32.f16.f16.f32 "
        "{%0,%1,%2,%3},{%4,%5,%6,%7},{%8,%9},{%0,%1,%2,%3};"
        : "+f"(d[0]), "+f"(d[1]), "+f"(d[2]), "+f"(d[3])
        : "r"(a[0]), "r"(a[1]), "r"(a[2]), "r"(a[3]), "r"(b[0]), "r"(b[1]));
}
__device__ __forceinline__ uint2 cvt4(float4 v) {
    __half2 a = __floats2half2_rn(v.x, v.y);
    __half2 b = __floats2half2_rn(v.z, v.w);
    return make_uint2(*(uint32_t*)&a, *(uint32_t*)&b);
}
__device__ __forceinline__ void cp16(uint32_t dst, const void* src) {
    asm volatile("cp.async.cg.shared.global [%0], [%1], 16;" :: "r"(dst), "l"(src));
}
__device__ __forceinline__ void cp16z(uint32_t dst, const void* src, uint32_t sz) {
    asm volatile("cp.async.cg.shared.global [%0], [%1], 16, %2;" :: "r"(dst), "l"(src), "r"(sz));
}
#define CP_COMMIT() asm volatile("cp.async.commit_group;" ::: "memory")
#define CP_WAIT1()  asm volatile("cp.async.wait_group 1;" ::: "memory")
#define CP_WAIT0()  asm volatile("cp.async.wait_group 0;" ::: "memory")

// ---------------- weight fp32 -> fp16 prepass ----------------
__global__ void cvt_kernel(const float4* __restrict__ src, uint2* __restrict__ dst, int n4) {
    int i = blockIdx.x * blockDim.x + threadIdx.x;
    if (i < n4) dst[i] = cvt4(src[i]);
}

// ---------------- small kernels ----------------
__global__ void init_kernel(float4* __restrict__ out4) {
    int i = blockIdx.x * blockDim.x + threadIdx.x;
    if (i < T_TOKENS * DDIM / 4) out4[i] = make_float4(0.f, 0.f, 0.f, 0.f);
    if (i < PAIRS_PAD) { g_pair_tok[i] = -1; g_pair_p[i] = 0.0f; }
    if (i < NEXP) g_cnt[i] = 0;
}

__global__ void router_kernel(const float* __restrict__ x, const float* __restrict__ wg) {
    int warp = (blockIdx.x * blockDim.x + threadIdx.x) >> 5;
    int lane = threadIdx.x & 31;
    if (warp >= T_TOKENS) return;
    const float4* xr4 = (const float4*)(x + (size_t)warp * DDIM);
    uint2* x16 = (uint2*)(g_X16 + (size_t)warp * DDIM);
    float acc[NEXP];
#pragma unroll
    for (int e = 0; e < NEXP; e++) acc[e] = 0.0f;
#pragma unroll
    for (int it = 0; it < 8; it++) {
        int d4 = lane + 32 * it;
        float4 v = xr4[d4];
        x16[d4] = cvt4(v);
        float xv[4] = {v.x, v.y, v.z, v.w};
#pragma unroll
        for (int j = 0; j < 4; j++) {
            const float4* wr = (const float4*)(wg + (size_t)(d4 * 4 + j) * NEXP);
            float4 w0 = wr[0], w1 = wr[1];
            acc[0] += xv[j] * w0.x; acc[1] += xv[j] * w0.y;
            acc[2] += xv[j] * w0.z; acc[3] += xv[j] * w0.w;
            acc[4] += xv[j] * w1.x; acc[5] += xv[j] * w1.y;
            acc[6] += xv[j] * w1.z; acc[7] += xv[j] * w1.w;
        }
    }
#pragma unroll
    for (int off = 16; off; off >>= 1)
#pragma unroll
        for (int e = 0; e < NEXP; e++)
            acc[e] += __shfl_xor_sync(0xffffffffu, acc[e], off);
    if (lane == 0) {
        int i0 = 0;
#pragma unroll
        for (int e = 1; e < NEXP; e++) if (acc[e] > acc[i0]) i0 = e;
        int i1 = (i0 == 0) ? 1 : 0;
#pragma unroll
        for (int e = 0; e < NEXP; e++)
            if (e != i0 && acc[e] > acc[i1]) i1 = e;
        float p1 = expf(acc[i1] - acc[i0]);
        float z = 1.0f + p1;
        g_tok_e[warp * 2 + 0] = i0; g_tok_p[warp * 2 + 0] = 1.0f / z;
        g_tok_e[warp * 2 + 1] = i1; g_tok_p[warp * 2 + 1] = p1 / z;
        atomicAdd(&g_cnt[i0], 1);
        atomicAdd(&g_cnt[i1], 1);
    }
}

__global__ void scan_kernel() {
    int tot = 0;
    for (int e = 0; e < NEXP; e++) {
        g_segs[e] = tot;
        g_fill[e] = tot;
        tot += ((g_cnt[e] + BM - 1) / BM) * BM;
    }
    g_segs[NEXP] = tot;
}

__global__ void scatter_kernel() {
    int t = blockIdx.x * blockDim.x + threadIdx.x;
    if (t >= T_TOKENS) return;
#pragma unroll
    for (int k = 0; k < 2; k++) {
        int e = g_tok_e[t * 2 + k];
        int pos = atomicAdd(&g_fill[e], 1);
        g_pair_tok[pos] = t;
        g_pair_p[pos]   = g_tok_p[t * 2 + k];
    }
}

// ---------------- GEMM1: CTA 128x64, warp 32x32, BK=64, 2-stage, 2 CTA/SM ----------------
#define S1_A     0
#define S1_BG    18432
#define S1_BU    27648
#define S1_STAGE 36864
#define S1_TOK   73728
#define S1_SE    74240
#define S1_SIZE  74256

__global__ __launch_bounds__(256, 2) void gemm1_kernel() {
    extern __shared__ __align__(128) char sm[];
    const uint32_t sb = smem_u32(sm);
    const int tid = threadIdx.x;
    const int lane = tid & 31, warp = tid >> 5;
    const int wm = warp >> 1, wn = warp & 1;     // 4 x 2 warps, tile 32x32
    const int p0 = blockIdx.x * BM;
    const int m0 = blockIdx.y * BN;

    if (tid == 0) {
        int e = -1;
        if (p0 < g_segs[NEXP]) { e = 0; while (p0 >= g_segs[e + 1]) e++; }
        *(int*)(sm + S1_SE) = e;
    }
    int* tokp = (int*)(sm + S1_TOK);
    if (tid < BM) tokp[tid] = g_pair_tok[p0 + tid];
    __syncthreads();
    const int e = *(int*)(sm + S1_SE);
    if (e < 0) return;

    const __half* Wg = g_Wg16 + (size_t)e * DDIM * MDIM;
    const __half* Wu = g_Wu16 + (size_t)e * DDIM * MDIM;

    // cp.async mappings: A 128 rows x 8 granules (4/thread); B 64 rows x 8 (2/thread each)
    const int a_row = tid >> 1, a_q0 = (tid & 1) * 4;
    const int tokA = tokp[a_row];
    const uint32_t a_sz = tokA >= 0 ? 16u : 0u;
    const __half* a_src = g_X16 + (size_t)(tokA < 0 ? 0 : tokA) * DDIM;

    float accG[2][4][4], accU[2][4][4];
#pragma unroll
    for (int i = 0; i < 2; i++)
#pragma unroll
        for (int j = 0; j < 4; j++)
#pragma unroll
            for (int q = 0; q < 4; q++) { accG[i][j][q] = 0.f; accU[i][j][q] = 0.f; }

    const int lm_off = ((lane >> 3) & 1) * 8 + (lane & 7);
    const int lm_hi  = (lane >> 4) * 8;
    const uint32_t aA0 = sb + S1_A + (wm * 32 + lm_off) * RS + lm_hi * 2;
    const uint32_t bG0 = sb + S1_BG + lm_off * RS + (wn * 32 + lm_hi) * 2;
    const uint32_t bU0 = sb + S1_BU + lm_off * RS + (wn * 32 + lm_hi) * 2;

    auto issue = [&](int ch) {
        const uint32_t st = sb + (ch & 1) * S1_STAGE;
        const int kk = ch * BK;
#pragma unroll
        for (int i = 0; i < 4; i++) {
            int q = a_q0 + i;
            cp16z(st + S1_A + a_row * RS + q * 16, a_src + kk + q * 8, a_sz);
        }
#pragma unroll
        for (int i = 0; i < 2; i++) {
            int idx = tid + 256 * i;
            int row = idx >> 3, q = idx & 7;
            cp16(st + S1_BG + row * RS + q * 16, Wg + (size_t)(kk + row) * MDIM + m0 + q * 8);
            cp16(st + S1_BU + row * RS + q * 16, Wu + (size_t)(kk + row) * MDIM + m0 + q * 8);
        }
    };

    issue(0); CP_COMMIT();

    for (int ch = 0; ch < G1_CH; ch++) {
        if (ch + 1 < G1_CH) { issue(ch + 1); CP_COMMIT(); CP_WAIT1(); }
        else CP_WAIT0();
        __syncthreads();
        const uint32_t so = (ch & 1) * S1_STAGE;
#pragma unroll
        for (int kh = 0; kh < 4; kh++) {
            uint32_t A[8];
            ldsm_x4(A + 0, aA0 + so + kh * 32);
            ldsm_x4(A + 4, aA0 + so + 2304 + kh * 32);
            uint32_t Bg[8], Bu[8];
            ldsm_x4_t(Bg + 0, bG0 + so + kh * 2304);
            ldsm_x4_t(Bg + 4, bG0 + so + kh * 2304 + 32);
            ldsm_x4_t(Bu + 0, bU0 + so + kh * 2304);
            ldsm_x4_t(Bu + 4, bU0 + so + kh * 2304 + 32);
#pragma unroll
            for (int mi = 0; mi < 2; mi++)
#pragma unroll
                for (int nf = 0; nf < 4; nf++) {
                    const uint32_t* bg = &Bg[(nf >> 1) * 4 + (nf & 1) * 2];
                    const uint32_t* bu = &Bu[(nf >> 1) * 4 + (nf & 1) * 2];
                    mma16816(accG[mi][nf], &A[mi * 4], bg);
                    mma16816(accU[mi][nf], &A[mi * 4], bu);
                }
        }
        __syncthreads();
    }

    // epilogue: SwiGLU -> fp16 store
    const int rg = lane >> 2, cg = (lane & 3) * 2;
#pragma unroll
    for (int mi = 0; mi < 2; mi++)
#pragma unroll
        for (int nf = 0; nf < 4; nf++) {
            const float* g = accG[mi][nf];
            const float* u = accU[mi][nf];
            int c = wn * 32 + nf * 8 + cg;
            size_t b0 = (size_t)(p0 + wm * 32 + mi * 16 + rg) * MDIM + m0 + c;
            size_t b1 = b0 + (size_t)8 * MDIM;
            float h0 = g[0] / (1.f + __expf(-g[0])) * u[0];
            float h1 = g[1] / (1.f + __expf(-g[1])) * u[1];
            float h2 = g[2] / (1.f + __expf(-g[2])) * u[2];
            float h3 = g[3] / (1.f + __expf(-g[3])) * u[3];
            *(__half2*)&g_Hf[b0] = __floats2half2_rn(h0, h1);
            *(__half2*)&g_Hf[b1] = __floats2half2_rn(h2, h3);
        }
}

// ---------------- GEMM2: CTA 128x64, warp 32x32, BK=64, 2-stage, 2 CTA/SM ----------------
#define S2_A     0
#define S2_B     18432
#define S2_STAGE 27648
#define S2_TOK   55296
#define S2_PRB   55808
#define S2_SE    56320
#define S2_SIZE  56336

__global__ __launch_bounds__(256, 2) void gemm2_kernel(float* __restrict__ out) {
    extern __shared__ __align__(128) char sm[];
    const uint32_t sb = smem_u32(sm);
    const int tid = threadIdx.x;
    const int lane = tid & 31, warp = tid >> 5;
    const int wm = warp >> 1, wn = warp & 1;
    const int p0 = blockIdx.x * BM;
    const int d0 = blockIdx.y * BN;

    if (tid == 0) {
        int e = -1;
        if (p0 < g_segs[NEXP]) { e = 0; while (p0 >= g_segs[e + 1]) e++; }
        *(int*)(sm + S2_SE) = e;
    }
    int* tokp = (int*)(sm + S2_TOK);
    float* prbp = (float*)(sm + S2_PRB);
    if (tid < BM) {
        tokp[tid] = g_pair_tok[p0 + tid];
        prbp[tid] = g_pair_p[p0 + tid];
    }
    __syncthreads();
    const int e = *(int*)(sm + S2_SE);
    if (e < 0) return;

    const __half* Wd = g_Wd16 + (size_t)e * MDIM * DDIM;
    const int a_row = tid >> 1, a_q0 = (tid & 1) * 4;
    const __half* a_src = g_Hf + (size_t)(p0 + a_row) * MDIM;

    float acc[2][4][4];
#pragma unroll
    for (int i = 0; i < 2; i++)
#pragma unroll
        for (int j = 0; j < 4; j++)
#pragma unroll
            for (int q = 0; q < 4; q++) acc[i][j][q] = 0.f;

    const int lm_off = ((lane >> 3) & 1) * 8 + (lane & 7);
    const int lm_hi  = (lane >> 4) * 8;
    const uint32_t aA0 = sb + S2_A + (wm * 32 + lm_off) * RS + lm_hi * 2;
    const uint32_t bB0 = sb + S2_B + lm_off * RS + (wn * 32 + lm_hi) * 2;

    auto issue = [&](int ch) {
        const uint32_t st = sb + (ch & 1) * S2_STAGE;
        const int kk = ch * BK;
#pragma unroll
        for (int i = 0; i < 4; i++) {
            int q = a_q0 + i;
            cp16(st + S2_A + a_row * RS + q * 16, a_src + kk + q * 8);
        }
#pragma unroll
        for (int i = 0; i < 2; i++) {
            int idx = tid + 256 * i;
            int row = idx >> 3, q = idx & 7;
            cp16(st + S2_B + row * RS + q * 16, Wd + (size_t)(kk + row) * DDIM + d0 + q * 8);
        }
    };

    issue(0); CP_COMMIT();

    for (int ch = 0; ch < G2_CH; ch++) {
        if (ch + 1 < G2_CH) { issue(ch + 1); CP_COMMIT(); CP_WAIT1(); }
        else CP_WAIT0();
        __syncthreads();
        const uint32_t so = (ch & 1) * S2_STAGE;
#pragma unroll
        for (int kh = 0; kh < 4; kh++) {
            uint32_t A[8];
            ldsm_x4(A + 0, aA0 + so + kh * 32);
            ldsm_x4(A + 4, aA0 + so + 2304 + kh * 32);
            uint32_t B[8];
            ldsm_x4_t(B + 0, bB0 + so + kh * 2304);
            ldsm_x4_t(B + 4, bB0 + so + kh * 2304 + 32);
#pragma unroll
            for (int mi = 0; mi < 2; mi++)
#pragma unroll
                for (int nf = 0; nf < 4; nf++)
                    mma16816(acc[mi][nf], &A[mi * 4], &B[(nf >> 1) * 4 + (nf & 1) * 2]);
        }
        __syncthreads();
    }

    // epilogue: prob-scaled atomic combine
    const int rg = lane >> 2, cg = (lane & 3) * 2;
#pragma unroll
    for (int mi = 0; mi < 2; mi++)
#pragma unroll
        for (int nf = 0; nf < 4; nf++) {
            const float* d = acc[mi][nf];
            int c = wn * 32 + nf * 8 + cg;
            int r0 = wm * 32 + mi * 16 + rg, r1 = r0 + 8;
            int t0 = tokp[r0], t1 = tokp[r1];
            if (t0 >= 0) {
                float p = prbp[r0];
                float* o = out + (size_t)t0 * DDIM + d0 + c;
                atomicAdd(o, p * d[0]);
                atomicAdd(o + 1, p * d[1]);
            }
            if (t1 >= 0) {
                float p = prbp[r1];
                float* o = out + (size_t)t1 * DDIM + d0 + c;
                atomicAdd(o, p * d[2]);
                atomicAdd(o + 1, p * d[3]);
            }
        }
}

// ---------------- launch ----------------
extern "C" void kernel_launch(void* const* d_in, const int* in_sizes, int n_in,
                              void* d_out, int out_size) {
    const float* x      = (const float*)d_in[0];
    const float* w_gate = (const float*)d_in[1];
    const float* w_g    = (const float*)d_in[2];
    const float* w_u    = (const float*)d_in[3];
    const float* w_d    = (const float*)d_in[4];
    float* out = (float*)d_out;

    __half* wg16; cudaGetSymbolAddress((void**)&wg16, g_Wg16);
    __half* wu16; cudaGetSymbolAddress((void**)&wu16, g_Wu16);
    __half* wd16; cudaGetSymbolAddress((void**)&wd16, g_Wd16);

    cudaFuncSetAttribute(gemm1_kernel, cudaFuncAttributeMaxDynamicSharedMemorySize, S1_SIZE);
    cudaFuncSetAttribute(gemm2_kernel, cudaFuncAttributeMaxDynamicSharedMemorySize, S2_SIZE);

    const int NW4 = NEXP * DDIM * MDIM / 4;
    init_kernel<<<(T_TOKENS * DDIM / 4 + 255) / 256, 256>>>((float4*)out);
    cvt_kernel<<<(NW4 + 255) / 256, 256>>>((const float4*)w_g, (uint2*)wg16, NW4);
    cvt_kernel<<<(NW4 + 255) / 256, 256>>>((const float4*)w_u, (uint2*)wu16, NW4);
    cvt_kernel<<<(NW4 + 255) / 256, 256>>>((const float4*)w_d, (uint2*)wd16, NW4);
    router_kernel<<<(T_TOKENS * 32 + 255) / 256, 256>>>(x, w_gate);
    scan_kernel<<<1, 1>>>();
    scatter_kernel<<<(T_TOKENS + 255) / 256, 256>>>();
    gemm1_kernel<<<dim3(NTILES, MDIM / BN), 256, S1_SIZE>>>();
    gemm2_kernel<<<dim3(NTILES, DDIM / BN), 256, S2_SIZE>>>(out);
}

// round 8
// speedup vs baseline: 1.3244x; 1.3244x over previous
#include <cuda_runtime.h>
#include <cuda_bf16.h>
#include <cuda_fp16.h>
#include <cstdint>
#include <math.h>

// ---------------- problem constants ----------------
#define T_TOKENS 4096
#define DDIM     1024
#define MDIM     1408
#define NEXP     8
#define BM       128
#define BN       64
#define BN2      128
#define PAIRS_PAD 9216
#define NTILES   (PAIRS_PAD / BM)     // 72
#define G1_CH    (DDIM / 32)          // 32
#define G2_CH    (MDIM / 32)          // 44

// ---------------- device scratch ----------------
__device__ __half g_Hf[(size_t)PAIRS_PAD * MDIM];
__device__ int   g_pair_tok[PAIRS_PAD];
__device__ float g_pair_p[PAIRS_PAD];
__device__ int   g_cnt[NEXP];
__device__ int   g_fill[NEXP];
__device__ int   g_segs[NEXP + 1];
__device__ int   g_tok_e[T_TOKENS * 2];
__device__ float g_tok_p[T_TOKENS * 2];

// ---------------- helpers ----------------
__device__ __forceinline__ uint32_t smem_u32(const void* p) {
    uint32_t a;
    asm("{ .reg .u64 t; cvta.to.shared.u64 t, %1; cvt.u32.u64 %0, t; }" : "=r"(a) : "l"(p));
    return a;
}
__device__ __forceinline__ void ldsm_x4(uint32_t* r, uint32_t addr) {
    asm volatile("ldmatrix.sync.aligned.m8n8.x4.shared.b16 {%0,%1,%2,%3}, [%4];"
        : "=r"(r[0]), "=r"(r[1]), "=r"(r[2]), "=r"(r[3]) : "r"(addr));
}
__device__ __forceinline__ void ldsm_x4_t(uint32_t* r, uint32_t addr) {
    asm volatile("ldmatrix.sync.aligned.m8n8.x4.trans.shared.b16 {%0,%1,%2,%3}, [%4];"
        : "=r"(r[0]), "=r"(r[1]), "=r"(r[2]), "=r"(r[3]) : "r"(addr));
}
__device__ __forceinline__ void mma16816(float* d, const uint32_t* a, const uint32_t* b) {
    asm volatile("mma.sync.aligned.m16n8k16.row.col.f32.f16.f16.f32 "
        "{%0,%1,%2,%3},{%4,%5,%6,%7},{%8,%9},{%0,%1,%2,%3};"
        : "+f"(d[0]), "+f"(d[1]), "+f"(d[2]), "+f"(d[3])
        : "r"(a[0]), "r"(a[1]), "r"(a[2]), "r"(a[3]), "r"(b[0]), "r"(b[1]));
}
__device__ __forceinline__ uint2 cvt4(float4 v) {
    __half2 a = __floats2half2_rn(v.x, v.y);
    __half2 b = __floats2half2_rn(v.z, v.w);
    return make_uint2(*(uint32_t*)&a, *(uint32_t*)&b);
}

// ---------------- small kernels ----------------
__global__ void init_kernel(float4* __restrict__ out4) {
    int i = blockIdx.x * blockDim.x + threadIdx.x;
    if (i < T_TOKENS * DDIM / 4) out4[i] = make_float4(0.f, 0.f, 0.f, 0.f);
    if (i < PAIRS_PAD) { g_pair_tok[i] = -1; g_pair_p[i] = 0.0f; }
    if (i < NEXP) g_cnt[i] = 0;
}

__global__ void router_kernel(const float* __restrict__ x, const float* __restrict__ wg) {
    int warp = (blockIdx.x * blockDim.x + threadIdx.x) >> 5;
    int lane = threadIdx.x & 31;
    if (warp >= T_TOKENS) return;
    const float* xr = x + (size_t)warp * DDIM;
    float acc[NEXP];
#pragma unroll
    for (int e = 0; e < NEXP; e++) acc[e] = 0.0f;
    for (int d = lane; d < DDIM; d += 32) {
        float xv = xr[d];
        const float4* wr = (const float4*)(wg + (size_t)d * NEXP);
        float4 w0 = wr[0], w1 = wr[1];
        acc[0] += xv * w0.x; acc[1] += xv * w0.y;
        acc[2] += xv * w0.z; acc[3] += xv * w0.w;
        acc[4] += xv * w1.x; acc[5] += xv * w1.y;
        acc[6] += xv * w1.z; acc[7] += xv * w1.w;
    }
#pragma unroll
    for (int off = 16; off; off >>= 1)
#pragma unroll
        for (int e = 0; e < NEXP; e++)
            acc[e] += __shfl_xor_sync(0xffffffffu, acc[e], off);
    if (lane == 0) {
        int i0 = 0;
#pragma unroll
        for (int e = 1; e < NEXP; e++) if (acc[e] > acc[i0]) i0 = e;
        int i1 = (i0 == 0) ? 1 : 0;
#pragma unroll
        for (int e = 0; e < NEXP; e++)
            if (e != i0 && acc[e] > acc[i1]) i1 = e;
        float p1 = expf(acc[i1] - acc[i0]);
        float z = 1.0f + p1;
        g_tok_e[warp * 2 + 0] = i0; g_tok_p[warp * 2 + 0] = 1.0f / z;
        g_tok_e[warp * 2 + 1] = i1; g_tok_p[warp * 2 + 1] = p1 / z;
        atomicAdd(&g_cnt[i0], 1);
        atomicAdd(&g_cnt[i1], 1);
    }
}

__global__ void scan_kernel() {
    int tot = 0;
    for (int e = 0; e < NEXP; e++) {
        g_segs[e] = tot;
        g_fill[e] = tot;
        tot += ((g_cnt[e] + BM - 1) / BM) * BM;
    }
    g_segs[NEXP] = tot;
}

__global__ void scatter_kernel() {
    int t = blockIdx.x * blockDim.x + threadIdx.x;
    if (t >= T_TOKENS) return;
#pragma unroll
    for (int k = 0; k < 2; k++) {
        int e = g_tok_e[t * 2 + k];
        int pos = atomicAdd(&g_fill[e], 1);
        g_pair_tok[pos] = t;
        g_pair_p[pos]   = g_tok_p[t * 2 + k];
    }
}

// ---------------- GEMM1 (unchanged from R4 best) ----------------
#define S1_A    0
#define S1_BG   10240
#define S1_BU   14848
#define S1_TOK  19456
#define S1_SE   19968
#define S1_SIZE 19984

__global__ __launch_bounds__(256) void gemm1_kernel(const float* __restrict__ x,
                                                    const float* __restrict__ w_g,
                                                    const float* __restrict__ w_u) {
    __shared__ __align__(128) char sm[S1_SIZE];
    const uint32_t sb = smem_u32(sm);
    const int tid = threadIdx.x;
    const int lane = tid & 31, warp = tid >> 5;
    const int wm = warp >> 1, wn = warp & 1;
    const int p0 = blockIdx.x * BM;
    const int m0 = blockIdx.y * BN;

    if (tid == 0) {
        int e = -1;
        if (p0 < g_segs[NEXP]) { e = 0; while (p0 >= g_segs[e + 1]) e++; }
        *(int*)(sm + S1_SE) = e;
    }
    int* tokp = (int*)(sm + S1_TOK);
    if (tid < BM) tokp[tid] = g_pair_tok[p0 + tid];
    __syncthreads();
    const int e = *(int*)(sm + S1_SE);
    if (e < 0) return;

    const float* Wg = w_g + (size_t)e * DDIM * MDIM;
    const float* Wu = w_u + (size_t)e * DDIM * MDIM;

    const int a_row = tid >> 3, a_kq = (tid & 7) * 4;
    const int b_k = tid >> 4, b_nq = (tid & 15) * 4;
    const int tokA0 = tokp[a_row], tokA1 = tokp[a_row + 32],
              tokA2 = tokp[a_row + 64], tokA3 = tokp[a_row + 96];

    float accG[2][4][4], accU[2][4][4];
#pragma unroll
    for (int i = 0; i < 2; i++)
#pragma unroll
        for (int j = 0; j < 4; j++)
#pragma unroll
            for (int q = 0; q < 4; q++) { accG[i][j][q] = 0.f; accU[i][j][q] = 0.f; }

    const int lm_off = ((lane >> 3) & 1) * 8 + (lane & 7);
    const int lm_hi  = (lane >> 4) * 8;
    const uint32_t aA0 = sb + S1_A + (wm * 32 + lm_off) * 80 + lm_hi * 2;
    const uint32_t bG0 = sb + S1_BG + lm_off * 144 + (wn * 32 + lm_hi) * 2;
    const uint32_t bU0 = sb + S1_BU + lm_off * 144 + (wn * 32 + lm_hi) * 2;

    float4 stA[4], stG[2], stU[2];
    {
        const int kk = 0;
        stA[0] = tokA0 >= 0 ? *(const float4*)(x + (size_t)tokA0 * DDIM + kk + a_kq) : make_float4(0, 0, 0, 0);
        stA[1] = tokA1 >= 0 ? *(const float4*)(x + (size_t)tokA1 * DDIM + kk + a_kq) : make_float4(0, 0, 0, 0);
        stA[2] = tokA2 >= 0 ? *(const float4*)(x + (size_t)tokA2 * DDIM + kk + a_kq) : make_float4(0, 0, 0, 0);
        stA[3] = tokA3 >= 0 ? *(const float4*)(x + (size_t)tokA3 * DDIM + kk + a_kq) : make_float4(0, 0, 0, 0);
        stG[0] = *(const float4*)(Wg + (size_t)(kk + b_k) * MDIM + m0 + b_nq);
        stG[1] = *(const float4*)(Wg + (size_t)(kk + b_k + 16) * MDIM + m0 + b_nq);
        stU[0] = *(const float4*)(Wu + (size_t)(kk + b_k) * MDIM + m0 + b_nq);
        stU[1] = *(const float4*)(Wu + (size_t)(kk + b_k + 16) * MDIM + m0 + b_nq);
    }

    for (int ch = 0; ch < G1_CH; ch++) {
#pragma unroll
        for (int i = 0; i < 4; i++)
            *(uint2*)(sm + S1_A + (a_row + i * 32) * 80 + a_kq * 2) = cvt4(stA[i]);
#pragma unroll
        for (int i = 0; i < 2; i++) {
            uint32_t off = (b_k + i * 16) * 144 + b_nq * 2;
            *(uint2*)(sm + S1_BG + off) = cvt4(stG[i]);
            *(uint2*)(sm + S1_BU + off) = cvt4(stU[i]);
        }
        __syncthreads();
        if (ch + 1 < G1_CH) {
            const int kk = (ch + 1) * 32;
            stA[0] = tokA0 >= 0 ? *(const float4*)(x + (size_t)tokA0 * DDIM + kk + a_kq) : make_float4(0, 0, 0, 0);
            stA[1] = tokA1 >= 0 ? *(const float4*)(x + (size_t)tokA1 * DDIM + kk + a_kq) : make_float4(0, 0, 0, 0);
            stA[2] = tokA2 >= 0 ? *(const float4*)(x + (size_t)tokA2 * DDIM + kk + a_kq) : make_float4(0, 0, 0, 0);
            stA[3] = tokA3 >= 0 ? *(const float4*)(x + (size_t)tokA3 * DDIM + kk + a_kq) : make_float4(0, 0, 0, 0);
            stG[0] = *(const float4*)(Wg + (size_t)(kk + b_k) * MDIM + m0 + b_nq);
            stG[1] = *(const float4*)(Wg + (size_t)(kk + b_k + 16) * MDIM + m0 + b_nq);
            stU[0] = *(const float4*)(Wu + (size_t)(kk + b_k) * MDIM + m0 + b_nq);
            stU[1] = *(const float4*)(Wu + (size_t)(kk + b_k + 16) * MDIM + m0 + b_nq);
        }
#pragma unroll
        for (int kh = 0; kh < 2; kh++) {
            uint32_t A[8];
            ldsm_x4(A + 0, aA0 + kh * 32);
            ldsm_x4(A + 4, aA0 + 1280 + kh * 32);
            uint32_t Bg[8], Bu[8];
            ldsm_x4_t(Bg + 0, bG0 + kh * 2304);
            ldsm_x4_t(Bg + 4, bG0 + kh * 2304 + 32);
            ldsm_x4_t(Bu + 0, bU0 + kh * 2304);
            ldsm_x4_t(Bu + 4, bU0 + kh * 2304 + 32);
#pragma unroll
            for (int mi = 0; mi < 2; mi++)
#pragma unroll
                for (int nf = 0; nf < 4; nf++) {
                    const uint32_t* bg = &Bg[(nf >> 1) * 4 + (nf & 1) * 2];
                    const uint32_t* bu = &Bu[(nf >> 1) * 4 + (nf & 1) * 2];
                    mma16816(accG[mi][nf], &A[mi * 4], bg);
                    mma16816(accU[mi][nf], &A[mi * 4], bu);
                }
        }
        __syncthreads();
    }

    const int rg = lane >> 2, cg = (lane & 3) * 2;
#pragma unroll
    for (int mi = 0; mi < 2; mi++)
#pragma unroll
        for (int nf = 0; nf < 4; nf++) {
            const float* g = accG[mi][nf];
            const float* u = accU[mi][nf];
            int c = wn * 32 + nf * 8 + cg;
            size_t b0 = (size_t)(p0 + wm * 32 + mi * 16 + rg) * MDIM + m0 + c;
            size_t b1 = b0 + (size_t)8 * MDIM;
            float h0 = g[0] / (1.f + __expf(-g[0])) * u[0];
            float h1 = g[1] / (1.f + __expf(-g[1])) * u[1];
            float h2 = g[2] / (1.f + __expf(-g[2])) * u[2];
            float h3 = g[3] / (1.f + __expf(-g[3])) * u[3];
            *(__half2*)&g_Hf[b0] = __floats2half2_rn(h0, h1);
            *(__half2*)&g_Hf[b1] = __floats2half2_rn(h2, h3);
        }
}

// ---------------- GEMM2: CTA 128x128, warp 64x32 (2x4), BK=32 ----------------
// A: 128 rows x 80B stride; B: 32 k-rows x 272B stride (256B + 16B skew)
#define S2_A    0
#define S2_B    10240
#define S2_TOK  18944
#define S2_PRB  19456
#define S2_SE   19968
#define S2_SIZE 19984

__global__ __launch_bounds__(256) void gemm2_kernel(const float* __restrict__ w_d,
                                                    float* __restrict__ out) {
    __shared__ __align__(128) char sm[S2_SIZE];
    const uint32_t sb = smem_u32(sm);
    const int tid = threadIdx.x;
    const int lane = tid & 31, warp = tid >> 5;
    const int wm = warp >> 2, wn = warp & 3;   // 2 x 4 warps, warp tile 64x32
    const int p0 = blockIdx.x * BM;
    const int d0 = blockIdx.y * BN2;

    if (tid == 0) {
        int e = -1;
        if (p0 < g_segs[NEXP]) { e = 0; while (p0 >= g_segs[e + 1]) e++; }
        *(int*)(sm + S2_SE) = e;
    }
    int* tokp = (int*)(sm + S2_TOK);
    float* prbp = (float*)(sm + S2_PRB);
    if (tid < BM) {
        tokp[tid] = g_pair_tok[p0 + tid];
        prbp[tid] = g_pair_p[p0 + tid];
    }
    __syncthreads();
    const int e = *(int*)(sm + S2_SE);
    if (e < 0) return;

    const float* Wd = w_d + (size_t)e * MDIM * DDIM;

    // A staging: 128 rows x 4 uint4-granules (BK=32 fp16), 2 per thread
    const int a_row = tid >> 2, a_q = tid & 3;
    // B staging: 32 k-rows x 32 float4-granules (128 fp32 cols), 4 per thread, coalesced
    const int b_r = tid >> 5, b_q = tid & 31;   // warp w covers row b_r (+8 per iter)

    float acc[4][4][4];
#pragma unroll
    for (int i = 0; i < 4; i++)
#pragma unroll
        for (int j = 0; j < 4; j++)
#pragma unroll
            for (int q = 0; q < 4; q++) acc[i][j][q] = 0.f;

    const int lm_off = ((lane >> 3) & 1) * 8 + (lane & 7);
    const int lm_hi  = (lane >> 4) * 8;
    const uint32_t aA0 = sb + S2_A + (wm * 64 + lm_off) * 80 + lm_hi * 2;
    const uint32_t bB0 = sb + S2_B + lm_off * 272 + (wn * 32 + lm_hi) * 2;

    uint4 stA[2];
    float4 stB[4];
    {
        const int kk = 0;
#pragma unroll
        for (int i = 0; i < 2; i++)
            stA[i] = *(const uint4*)&g_Hf[(size_t)(p0 + a_row + i * 64) * MDIM + kk + a_q * 8];
#pragma unroll
        for (int i = 0; i < 4; i++)
            stB[i] = *(const float4*)(Wd + (size_t)(kk + b_r + i * 8) * DDIM + d0 + b_q * 4);
    }

    for (int ch = 0; ch < G2_CH; ch++) {
#pragma unroll
        for (int i = 0; i < 2; i++)
            *(uint4*)(sm + S2_A + (a_row + i * 64) * 80 + a_q * 16) = stA[i];
#pragma unroll
        for (int i = 0; i < 4; i++)
            *(uint2*)(sm + S2_B + (b_r + i * 8) * 272 + b_q * 8) = cvt4(stB[i]);
        __syncthreads();
        if (ch + 1 < G2_CH) {
            const int kk = (ch + 1) * 32;
#pragma unroll
            for (int i = 0; i < 2; i++)
                stA[i] = *(const uint4*)&g_Hf[(size_t)(p0 + a_row + i * 64) * MDIM + kk + a_q * 8];
#pragma unroll
            for (int i = 0; i < 4; i++)
                stB[i] = *(const float4*)(Wd + (size_t)(kk + b_r + i * 8) * DDIM + d0 + b_q * 4);
        }
#pragma unroll
        for (int kh = 0; kh < 2; kh++) {
            uint32_t A[16];
#pragma unroll
            for (int f = 0; f < 4; f++)
                ldsm_x4(A + f * 4, aA0 + f * 1280 + kh * 32);
            uint32_t B[8];
            ldsm_x4_t(B + 0, bB0 + kh * 4352);
            ldsm_x4_t(B + 4, bB0 + kh * 4352 + 32);
#pragma unroll
            for (int mi = 0; mi < 4; mi++)
#pragma unroll
                for (int nf = 0; nf < 4; nf++)
                    mma16816(acc[mi][nf], &A[mi * 4], &B[(nf >> 1) * 4 + (nf & 1) * 2]);
        }
        __syncthreads();
    }

    // epilogue: prob-scaled atomic combine
    const int rg = lane >> 2, cg = (lane & 3) * 2;
#pragma unroll
    for (int mi = 0; mi < 4; mi++)
#pragma unroll
        for (int nf = 0; nf < 4; nf++) {
            const float* d = acc[mi][nf];
            int c = wn * 32 + nf * 8 + cg;
            int r0 = wm * 64 + mi * 16 + rg, r1 = r0 + 8;
            int t0 = tokp[r0], t1 = tokp[r1];
            if (t0 >= 0) {
                float p = prbp[r0];
                float* o = out + (size_t)t0 * DDIM + d0 + c;
                atomicAdd(o, p * d[0]);
                atomicAdd(o + 1, p * d[1]);
            }
            if (t1 >= 0) {
                float p = prbp[r1];
                float* o = out + (size_t)t1 * DDIM + d0 + c;
                atomicAdd(o, p * d[2]);
                atomicAdd(o + 1, p * d[3]);
            }
        }
}

// ---------------- launch ----------------
extern "C" void kernel_launch(void* const* d_in, const int* in_sizes, int n_in,
                              void* d_out, int out_size) {
    const float* x      = (const float*)d_in[0];
    const float* w_gate = (const float*)d_in[1];
    const float* w_g    = (const float*)d_in[2];
    const float* w_u    = (const float*)d_in[3];
    const float* w_d    = (const float*)d_in[4];
    float* out = (float*)d_out;

    init_kernel<<<(T_TOKENS * DDIM / 4 + 255) / 256, 256>>>((float4*)out);
    router_kernel<<<(T_TOKENS * 32 + 255) / 256, 256>>>(x, w_gate);
    scan_kernel<<<1, 1>>>();
    scatter_kernel<<<(T_TOKENS + 255) / 256, 256>>>();
    gemm1_kernel<<<dim3(NTILES, MDIM / BN), 256>>>(x, w_g, w_u);
    gemm2_kernel<<<dim3(NTILES, DDIM / BN2), 256>>>(w_d, out);
}